// round 4
// baseline (speedup 1.0000x reference)
#include <cuda_runtime.h>

// ---------------- static scratch (no allocation allowed) ----------------
#define NMAX 50048
#define EMAX 900000
#define FMAX 128

__device__ int   d_deg[NMAX];
__device__ int   d_cur[NMAX];
__device__ int   d_off[NMAX + 1];
__device__ int   d_bsum[256];
__device__ int   d_csr[EMAX];
__device__ float d_HA[NMAX * FMAX];
__device__ float d_HB[NMAX * FMAX];
__device__ float d_asrc[NMAX];
__device__ float d_adst[NMAX];
__device__ float d_bn[256];          // [0:128) sum, [128:256) sumsq
__device__ float d_scale[FMAX];
__device__ float d_shift[FMAX];
__device__ float d_pooled[2048 * 64];

__device__ __forceinline__ float leaky(float x, float s) { return x > 0.f ? x : s * x; }

// ---------------- utility ----------------
__global__ void zero_i(int* p, int n) {
    int i = blockIdx.x * blockDim.x + threadIdx.x;
    if (i < n) p[i] = 0;
}
__global__ void zero_f(float* p, int n) {
    int i = blockIdx.x * blockDim.x + threadIdx.x;
    if (i < n) p[i] = 0.f;
}

// ---------------- CSR build (once per launch) ----------------
__global__ void count_deg(const int* __restrict__ ei, int E, int N, int* deg) {
    int e = blockIdx.x * blockDim.x + threadIdx.x;
    if (e >= E + N) return;
    int d = (e < E) ? ei[E + e] : (e - E);
    atomicAdd(&deg[d], 1);
}

__global__ void scan1(const int* __restrict__ deg, int* off, int* bsum, int N) {
    __shared__ int s[512];
    int i = blockIdx.x * 512 + threadIdx.x;
    int v = (i < N) ? deg[i] : 0;
    s[threadIdx.x] = v;
    __syncthreads();
    for (int d = 1; d < 512; d <<= 1) {
        int t = (threadIdx.x >= d) ? s[threadIdx.x - d] : 0;
        __syncthreads();
        s[threadIdx.x] += t;
        __syncthreads();
    }
    if (i < N) off[i + 1] = s[threadIdx.x];
    if (threadIdx.x == 511) bsum[blockIdx.x] = s[511];
}

__global__ void scan2(int* bsum, int nb) {
    __shared__ int s[128];
    int t = threadIdx.x;
    int v = (t < nb) ? bsum[t] : 0;
    s[t] = v;
    __syncthreads();
    for (int d = 1; d < 128; d <<= 1) {
        int x = (t >= d) ? s[t - d] : 0;
        __syncthreads();
        s[t] += x;
        __syncthreads();
    }
    if (t < nb) bsum[t] = s[t] - v;   // exclusive
}

__global__ void scan3(int* off, const int* __restrict__ bsum, int N) {
    int i = blockIdx.x * 512 + threadIdx.x;
    if (i < N) off[i + 1] += bsum[blockIdx.x];
    if (i == 0) off[0] = 0;
}

__global__ void fill_csr(const int* __restrict__ ei, int E, int N,
                         const int* __restrict__ off, int* cur, int* csr) {
    int e = blockIdx.x * blockDim.x + threadIdx.x;
    if (e >= E + N) return;
    int s, d;
    if (e < E) { s = ei[e]; d = ei[E + e]; }
    else       { s = d = e - E; }
    int p = atomicAdd(&cur[d], 1);
    csr[off[d] + p] = s;
}

// ---------------- tiled GEMM with fused BN-affine on load ----------------
// Y[N,DOUT] = affine(X)[N,DIN] @ W[DIN,DOUT];  affine(x)=x*scale[k]+shift[k] (or identity)
template <int DIN, int DOUT>
__global__ __launch_bounds__(256) void gemm_kernel(
    const float* __restrict__ X, const float* __restrict__ W,
    const float* __restrict__ scale, const float* __restrict__ shift,
    float* __restrict__ Y, int N)
{
    constexpr int TX = DOUT / 4;
    constexpr int TY = 256 / TX;
    constexpr int NODES = TY * 4;
    constexpr int KC = (DIN < 64) ? DIN : 64;

    __shared__ float sIn[NODES][KC + 1];
    __shared__ float sW[KC][DOUT];

    int tid = threadIdx.x;
    int tx = tid % TX, ty = tid / TX;
    int nodeBase = blockIdx.x * NODES;

    float acc[4][4] = {};

    for (int k0 = 0; k0 < DIN; k0 += KC) {
        for (int i = tid; i < KC * DOUT; i += 256)
            sW[i / DOUT][i % DOUT] = W[(k0 + i / DOUT) * DOUT + (i % DOUT)];
        for (int i = tid; i < NODES * KC; i += 256) {
            int r = i / KC, c = i % KC;
            int n = nodeBase + r;
            float v = 0.f;
            if (n < N) {
                v = X[n * DIN + k0 + c];
                if (scale) v = v * scale[k0 + c] + shift[k0 + c];
            }
            sIn[r][c] = v;
        }
        __syncthreads();

#pragma unroll 8
        for (int k = 0; k < KC; k++) {
            float4 w4 = *(const float4*)&sW[k][tx * 4];
            float xv[4];
#pragma unroll
            for (int r = 0; r < 4; r++) xv[r] = sIn[ty * 4 + r][k];
#pragma unroll
            for (int r = 0; r < 4; r++) {
                acc[r][0] += xv[r] * w4.x;
                acc[r][1] += xv[r] * w4.y;
                acc[r][2] += xv[r] * w4.z;
                acc[r][3] += xv[r] * w4.w;
            }
        }
        __syncthreads();
    }

#pragma unroll
    for (int r = 0; r < 4; r++) {
        int n = nodeBase + ty * 4 + r;
        if (n < N) {
            float4 o;
            o.x = acc[r][0]; o.y = acc[r][1]; o.z = acc[r][2]; o.w = acc[r][3];
            *(float4*)&Y[n * DOUT + tx * 4] = o;
        }
    }
}

// ---------------- attention dot products: asrc[n]=h[n]·a_s, adst[n]=h[n]·a_d ----------------
__global__ void attdot(const float* __restrict__ h, const float* __restrict__ a_s,
                       const float* __restrict__ a_d, float* __restrict__ asrc,
                       float* __restrict__ adst, int N, int dout)
{
    int warp = (blockIdx.x * blockDim.x + threadIdx.x) >> 5;
    int lane = threadIdx.x & 31;
    if (warp >= N) return;
    float s1 = 0.f, s2 = 0.f;
    for (int j = lane; j < dout; j += 32) {
        float v = h[warp * dout + j];
        s1 += v * a_s[j];
        s2 += v * a_d[j];
    }
#pragma unroll
    for (int o = 16; o; o >>= 1) {
        s1 += __shfl_xor_sync(0xffffffffu, s1, o);
        s2 += __shfl_xor_sync(0xffffffffu, s2, o);
    }
    if (lane == 0) { asrc[warp] = s1; adst[warp] = s2; }
}

// ---------------- fused softmax-attention aggregation, warp per dst node ----------------
// out[n] = leaky( sum_e alpha_e * h[src_e] + b , 0.01 )
template <int DOUT>
__global__ __launch_bounds__(256) void agg_kernel(
    const float* __restrict__ h, const float* __restrict__ asrc,
    const float* __restrict__ adst, const int* __restrict__ off,
    const int* __restrict__ csr, const float* __restrict__ bias,
    float* __restrict__ out, int N)
{
    int warp = (blockIdx.x * blockDim.x + threadIdx.x) >> 5;
    int lane = threadIdx.x & 31;
    if (warp >= N) return;
    int n = warp;
    int o0 = off[n], o1 = off[n + 1];
    float ad = adst[n];

    // pass A+B fused: online (max, sum of exp)
    float m = -1e30f, s = 0.f;
    for (int i = o0 + lane; i < o1; i += 32) {
        int src = csr[i];
        float e = asrc[src] + ad;
        e = leaky(e, 0.2f);
        if (e > m) { s *= __expf(m - e); m = e; }
        s += __expf(e - m);
    }
#pragma unroll
    for (int o = 16; o; o >>= 1) {
        float m2 = __shfl_xor_sync(0xffffffffu, m, o);
        float s2 = __shfl_xor_sync(0xffffffffu, s, o);
        float mm = fmaxf(m, m2);
        s = s * __expf(m - mm) + s2 * __expf(m2 - mm);
        m = mm;
    }
    float inv = 1.f / s;

    // pass C: weighted gather; lanes cover feature dim
    constexpr int F = DOUT / 32;
    float acc[F];
#pragma unroll
    for (int f = 0; f < F; f++) acc[f] = 0.f;

    for (int i = o0; i < o1; i++) {
        int src = csr[i];                 // broadcast
        float e = asrc[src] + ad;         // broadcast
        e = leaky(e, 0.2f);
        float alpha = __expf(e - m) * inv;
        const float* hrow = h + (size_t)src * DOUT + lane;
#pragma unroll
        for (int f = 0; f < F; f++)
            acc[f] += alpha * hrow[32 * f];
    }
#pragma unroll
    for (int f = 0; f < F; f++) {
        float v = acc[f] + bias[lane + 32 * f];
        out[n * DOUT + lane + 32 * f] = leaky(v, 0.01f);
    }
}

// ---------------- batchnorm statistics (sum, sumsq per feature) ----------------
template <int DOUT>
__global__ void bnstats(const float* __restrict__ act, float* bnsum, float* bnsq, int N)
{
    constexpr int ROWS = 256 / DOUT;
    int j = threadIdx.x % DOUT;
    int r = threadIdx.x / DOUT;
    float s = 0.f, q = 0.f;
    for (int n = blockIdx.x * ROWS + r; n < N; n += gridDim.x * ROWS) {
        float v = act[n * DOUT + j];
        s += v;
        q += v * v;
    }
    __shared__ float ss[256], sq[256];
    ss[threadIdx.x] = s;
    sq[threadIdx.x] = q;
    __syncthreads();
    if (r == 0) {
        for (int g = 1; g < ROWS; g++) { s += ss[g * DOUT + j]; q += sq[g * DOUT + j]; }
        atomicAdd(&bnsum[j], s);
        atomicAdd(&bnsq[j], q);
    }
}

__global__ void bnfin(const float* __restrict__ bnsum, const float* __restrict__ bnsq,
                      const float* __restrict__ g, const float* __restrict__ be,
                      float* scale, float* shift, int N, int dout)
{
    int j = threadIdx.x;
    if (j >= dout) return;
    float invN = 1.f / (float)N;
    float mu = bnsum[j] * invN;
    float var = bnsq[j] * invN - mu * mu;
    float sc = g[j] * rsqrtf(var + 1e-5f);
    scale[j] = sc;
    shift[j] = be[j] - mu * sc;
}

// ---------------- pooling (batch is sorted => run-length accumulate) ----------------
__global__ void pool_kernel(const float* __restrict__ act, const float* __restrict__ scale,
                            const float* __restrict__ shift, const int* __restrict__ batch,
                            float* pooled, int N)
{
    const int CHUNK = 32;
    int j = threadIdx.x;            // 0..63
    int n0 = blockIdx.x * CHUNK;
    int n1 = n0 + CHUNK; if (n1 > N) n1 = N;
    float sc = scale[j], sh = shift[j];
    float acc = 0.f;
    int cur = -1;
    for (int n = n0; n < n1; n++) {
        int b = batch[n];
        if (b != cur) {
            if (cur >= 0) atomicAdd(&pooled[cur * 64 + j], acc);
            cur = b; acc = 0.f;
        }
        acc += act[n * 64 + j] * sc + sh;
    }
    if (cur >= 0) atomicAdd(&pooled[cur * 64 + j], acc);
}

// ---------------- final MLP + sigmoid ----------------
__global__ void mlp_kernel(const float* __restrict__ pooled, const float* __restrict__ Wf,
                           const float* __restrict__ bf, const float* __restrict__ Wc,
                           const float* __restrict__ bc, float* __restrict__ out, int G)
{
    int g = blockIdx.x;
    __shared__ float p[64];
    __shared__ float z[32];
    int t = threadIdx.x;            // 64 threads
    p[t] = pooled[g * 64 + t];
    __syncthreads();
    if (t < 32) {
        float a = bf[t];
#pragma unroll 8
        for (int k = 0; k < 64; k++) a += p[k] * Wf[k * 32 + t];
        z[t] = leaky(a, 0.01f);
    }
    __syncthreads();
    if (t < 8) {
        float a = bc[t];
#pragma unroll
        for (int jj = 0; jj < 32; jj++) a += z[jj] * Wc[jj * 8 + t];
        out[g * 8 + t] = 1.f / (1.f + expf(-a));
    }
}

// ---------------- host launcher ----------------
extern "C" void kernel_launch(void* const* d_in, const int* in_sizes, int n_in,
                              void* d_out, int out_size)
{
    const float* x     = (const float*)d_in[0];
    const int*   ei    = (const int*)d_in[1];
    const int*   batch = (const int*)d_in[2];
    int N = in_sizes[2];
    int E = in_sizes[1] / 2;
    int G = out_size / 8;
    int ET = E + N;
    float* out = (float*)d_out;

    // parameter pointers (layer i base = 3 + 6*(i-1))
    const float *W[4], *As[4], *Ad[4], *B[4], *Gm[4], *Be[4];
    for (int i = 0; i < 4; i++) {
        int base = 3 + 6 * i;
        W[i]  = (const float*)d_in[base + 0];
        As[i] = (const float*)d_in[base + 1];
        Ad[i] = (const float*)d_in[base + 2];
        B[i]  = (const float*)d_in[base + 3];
        Gm[i] = (const float*)d_in[base + 4];
        Be[i] = (const float*)d_in[base + 5];
    }
    const float* Wf = (const float*)d_in[27];
    const float* bf = (const float*)d_in[28];
    const float* Wc = (const float*)d_in[29];
    const float* bc = (const float*)d_in[30];

    int *deg, *cur, *off, *bsum, *csr;
    float *HA, *HB, *asrc, *adst, *bn, *scale, *shift, *pooled;
    cudaGetSymbolAddress((void**)&deg,    d_deg);
    cudaGetSymbolAddress((void**)&cur,    d_cur);
    cudaGetSymbolAddress((void**)&off,    d_off);
    cudaGetSymbolAddress((void**)&bsum,   d_bsum);
    cudaGetSymbolAddress((void**)&csr,    d_csr);
    cudaGetSymbolAddress((void**)&HA,     d_HA);
    cudaGetSymbolAddress((void**)&HB,     d_HB);
    cudaGetSymbolAddress((void**)&asrc,   d_asrc);
    cudaGetSymbolAddress((void**)&adst,   d_adst);
    cudaGetSymbolAddress((void**)&bn,     d_bn);
    cudaGetSymbolAddress((void**)&scale,  d_scale);
    cudaGetSymbolAddress((void**)&shift,  d_shift);
    cudaGetSymbolAddress((void**)&pooled, d_pooled);

    // ---- build dst-CSR (reused by all 4 layers) ----
    zero_i<<<(N + 255) / 256, 256>>>(deg, N);
    zero_i<<<(N + 255) / 256, 256>>>(cur, N);
    count_deg<<<(ET + 255) / 256, 256>>>(ei, E, N, deg);
    int nb = (N + 511) / 512;
    scan1<<<nb, 512>>>(deg, off, bsum, N);
    scan2<<<1, 128>>>(bsum, nb);
    scan3<<<nb, 512>>>(off, bsum, N);
    fill_csr<<<(ET + 255) / 256, 256>>>(ei, E, N, off, cur, csr);

    int nwb = (N + 7) / 8;   // blocks for warp-per-node kernels (256 thr = 8 warps)

    // ---- layer 1: 128 -> 32 (input = x, no BN affine) ----
    gemm_kernel<128, 32><<<(N + 127) / 128, 256>>>(x, W[0], nullptr, nullptr, HA, N);
    attdot<<<nwb, 256>>>(HA, As[0], Ad[0], asrc, adst, N, 32);
    agg_kernel<32><<<nwb, 256>>>(HA, asrc, adst, off, csr, B[0], HB, N);
    zero_f<<<1, 256>>>(bn, 256);
    bnstats<32><<<256, 256>>>(HB, bn, bn + 128, N);
    bnfin<<<1, 128>>>(bn, bn + 128, Gm[0], Be[0], scale, shift, N, 32);

    // ---- layer 2: 32 -> 64 (BN of layer 1 folded into GEMM load) ----
    gemm_kernel<32, 64><<<(N + 63) / 64, 256>>>(HB, W[1], scale, shift, HA, N);
    attdot<<<nwb, 256>>>(HA, As[1], Ad[1], asrc, adst, N, 64);
    agg_kernel<64><<<nwb, 256>>>(HA, asrc, adst, off, csr, B[1], HB, N);
    zero_f<<<1, 256>>>(bn, 256);
    bnstats<64><<<256, 256>>>(HB, bn, bn + 128, N);
    bnfin<<<1, 128>>>(bn, bn + 128, Gm[1], Be[1], scale, shift, N, 64);

    // ---- layer 3: 64 -> 128 ----
    gemm_kernel<64, 128><<<(N + 31) / 32, 256>>>(HB, W[2], scale, shift, HA, N);
    attdot<<<nwb, 256>>>(HA, As[2], Ad[2], asrc, adst, N, 128);
    agg_kernel<128><<<nwb, 256>>>(HA, asrc, adst, off, csr, B[2], HB, N);
    zero_f<<<1, 256>>>(bn, 256);
    bnstats<128><<<256, 256>>>(HB, bn, bn + 128, N);
    bnfin<<<1, 128>>>(bn, bn + 128, Gm[2], Be[2], scale, shift, N, 128);

    // ---- layer 4: 128 -> 64 ----
    gemm_kernel<128, 64><<<(N + 63) / 64, 256>>>(HB, W[3], scale, shift, HA, N);
    attdot<<<nwb, 256>>>(HA, As[3], Ad[3], asrc, adst, N, 64);
    agg_kernel<64><<<nwb, 256>>>(HA, asrc, adst, off, csr, B[3], HB, N);
    zero_f<<<1, 256>>>(bn, 256);
    bnstats<64><<<256, 256>>>(HB, bn, bn + 128, N);
    bnfin<<<1, 128>>>(bn, bn + 128, Gm[3], Be[3], scale, shift, N, 64);

    // ---- pooling (layer-4 BN affine applied on the fly; batch sorted) ----
    zero_f<<<(G * 64 + 255) / 256, 256>>>(pooled, G * 64);
    pool_kernel<<<(N + 31) / 32, 64>>>(HB, scale, shift, batch, pooled, N);

    // ---- final MLP + sigmoid ----
    mlp_kernel<<<G, 64>>>(pooled, Wf, bf, Wc, bc, out, G);
}

// round 5
// speedup vs baseline: 1.0076x; 1.0076x over previous
#include <cuda_runtime.h>

// ---------------- static scratch (no allocation allowed) ----------------
#define NMAX 50048
#define EMAX 900000
#define FMAX 128

__device__ int   d_deg[NMAX];
__device__ int   d_cur[NMAX];
__device__ int   d_off[NMAX + 1];
__device__ int   d_bsum[256];
__device__ int   d_csr[EMAX];
__device__ float d_HA[NMAX * FMAX];
__device__ float d_HB[NMAX * FMAX];
__device__ float d_asrc[NMAX];
__device__ float d_adst[NMAX];
__device__ float d_bn[256];          // [0:128) sum, [128:256) sumsq
__device__ float d_scale[FMAX];
__device__ float d_shift[FMAX];
__device__ float d_pooled[2048 * 64];

__device__ __forceinline__ float leaky(float x, float s) { return x > 0.f ? x : s * x; }

// ---------------- utility ----------------
__global__ void zero_i(int* p, int n) {
    int i = blockIdx.x * blockDim.x + threadIdx.x;
    if (i < n) p[i] = 0;
}
__global__ void zero_f(float* p, int n) {
    int i = blockIdx.x * blockDim.x + threadIdx.x;
    if (i < n) p[i] = 0.f;
}

// ---------------- CSR build (once per launch) ----------------
__global__ void count_deg(const int* __restrict__ ei, int E, int N, int* deg) {
    int e = blockIdx.x * blockDim.x + threadIdx.x;
    if (e >= E + N) return;
    int d = (e < E) ? ei[E + e] : (e - E);
    atomicAdd(&deg[d], 1);
}

__global__ void scan1(const int* __restrict__ deg, int* off, int* bsum, int N) {
    __shared__ int s[512];
    int i = blockIdx.x * 512 + threadIdx.x;
    int v = (i < N) ? deg[i] : 0;
    s[threadIdx.x] = v;
    __syncthreads();
    for (int d = 1; d < 512; d <<= 1) {
        int t = (threadIdx.x >= d) ? s[threadIdx.x - d] : 0;
        __syncthreads();
        s[threadIdx.x] += t;
        __syncthreads();
    }
    if (i < N) off[i + 1] = s[threadIdx.x];
    if (threadIdx.x == 511) bsum[blockIdx.x] = s[511];
}

__global__ void scan2(int* bsum, int nb) {
    __shared__ int s[128];
    int t = threadIdx.x;
    int v = (t < nb) ? bsum[t] : 0;
    s[t] = v;
    __syncthreads();
    for (int d = 1; d < 128; d <<= 1) {
        int x = (t >= d) ? s[t - d] : 0;
        __syncthreads();
        s[t] += x;
        __syncthreads();
    }
    if (t < nb) bsum[t] = s[t] - v;   // exclusive
}

__global__ void scan3(int* off, const int* __restrict__ bsum, int N) {
    int i = blockIdx.x * 512 + threadIdx.x;
    if (i < N) off[i + 1] += bsum[blockIdx.x];
    if (i == 0) off[0] = 0;
}

__global__ void fill_csr(const int* __restrict__ ei, int E, int N,
                         const int* __restrict__ off, int* cur, int* csr) {
    int e = blockIdx.x * blockDim.x + threadIdx.x;
    if (e >= E + N) return;
    int s, d;
    if (e < E) { s = ei[e]; d = ei[E + e]; }
    else       { s = d = e - E; }
    int p = atomicAdd(&cur[d], 1);
    csr[off[d] + p] = s;
}

// ---------------- tiled GEMM with fused BN-affine on load ----------------
// Y[N,DOUT] = affine(X)[N,DIN] @ W[DIN,DOUT];  affine(x)=x*scale[k]+shift[k] (or identity)
template <int DIN, int DOUT>
__global__ __launch_bounds__(256) void gemm_kernel(
    const float* __restrict__ X, const float* __restrict__ W,
    const float* __restrict__ scale, const float* __restrict__ shift,
    float* __restrict__ Y, int N)
{
    constexpr int TX = DOUT / 4;
    constexpr int TY = 256 / TX;
    constexpr int NODES = TY * 4;
    constexpr int KC = (DIN < 64) ? DIN : 64;

    __shared__ float sIn[NODES][KC + 1];
    __shared__ float sW[KC][DOUT];

    int tid = threadIdx.x;
    int tx = tid % TX, ty = tid / TX;
    int nodeBase = blockIdx.x * NODES;

    float acc[4][4] = {};

    for (int k0 = 0; k0 < DIN; k0 += KC) {
        for (int i = tid; i < KC * DOUT; i += 256)
            sW[i / DOUT][i % DOUT] = W[(k0 + i / DOUT) * DOUT + (i % DOUT)];
        for (int i = tid; i < NODES * KC; i += 256) {
            int r = i / KC, c = i % KC;
            int n = nodeBase + r;
            float v = 0.f;
            if (n < N) {
                v = X[n * DIN + k0 + c];
                if (scale) v = v * scale[k0 + c] + shift[k0 + c];
            }
            sIn[r][c] = v;
        }
        __syncthreads();

#pragma unroll 8
        for (int k = 0; k < KC; k++) {
            float4 w4 = *(const float4*)&sW[k][tx * 4];
            float xv[4];
#pragma unroll
            for (int r = 0; r < 4; r++) xv[r] = sIn[ty * 4 + r][k];
#pragma unroll
            for (int r = 0; r < 4; r++) {
                acc[r][0] += xv[r] * w4.x;
                acc[r][1] += xv[r] * w4.y;
                acc[r][2] += xv[r] * w4.z;
                acc[r][3] += xv[r] * w4.w;
            }
        }
        __syncthreads();
    }

#pragma unroll
    for (int r = 0; r < 4; r++) {
        int n = nodeBase + ty * 4 + r;
        if (n < N) {
            float4 o;
            o.x = acc[r][0]; o.y = acc[r][1]; o.z = acc[r][2]; o.w = acc[r][3];
            *(float4*)&Y[n * DOUT + tx * 4] = o;
        }
    }
}

// ---------------- attention dot products: asrc[n]=h[n]·a_s, adst[n]=h[n]·a_d ----------------
__global__ void attdot(const float* __restrict__ h, const float* __restrict__ a_s,
                       const float* __restrict__ a_d, float* __restrict__ asrc,
                       float* __restrict__ adst, int N, int dout)
{
    int warp = (blockIdx.x * blockDim.x + threadIdx.x) >> 5;
    int lane = threadIdx.x & 31;
    if (warp >= N) return;
    float s1 = 0.f, s2 = 0.f;
    for (int j = lane; j < dout; j += 32) {
        float v = h[warp * dout + j];
        s1 += v * a_s[j];
        s2 += v * a_d[j];
    }
#pragma unroll
    for (int o = 16; o; o >>= 1) {
        s1 += __shfl_xor_sync(0xffffffffu, s1, o);
        s2 += __shfl_xor_sync(0xffffffffu, s2, o);
    }
    if (lane == 0) { asrc[warp] = s1; adst[warp] = s2; }
}

// ---------------- fused softmax-attention aggregation, warp per dst node ----------------
// out[n] = leaky( sum_e alpha_e * h[src_e] + b , 0.01 )
template <int DOUT>
__global__ __launch_bounds__(256) void agg_kernel(
    const float* __restrict__ h, const float* __restrict__ asrc,
    const float* __restrict__ adst, const int* __restrict__ off,
    const int* __restrict__ csr, const float* __restrict__ bias,
    float* __restrict__ out, int N)
{
    int warp = (blockIdx.x * blockDim.x + threadIdx.x) >> 5;
    int lane = threadIdx.x & 31;
    if (warp >= N) return;
    int n = warp;
    int o0 = off[n], o1 = off[n + 1];
    float ad = adst[n];

    // pass A+B fused: online (max, sum of exp)
    float m = -1e30f, s = 0.f;
    for (int i = o0 + lane; i < o1; i += 32) {
        int src = csr[i];
        float e = asrc[src] + ad;
        e = leaky(e, 0.2f);
        if (e > m) { s *= __expf(m - e); m = e; }
        s += __expf(e - m);
    }
#pragma unroll
    for (int o = 16; o; o >>= 1) {
        float m2 = __shfl_xor_sync(0xffffffffu, m, o);
        float s2 = __shfl_xor_sync(0xffffffffu, s, o);
        float mm = fmaxf(m, m2);
        s = s * __expf(m - mm) + s2 * __expf(m2 - mm);
        m = mm;
    }
    float inv = 1.f / s;

    // pass C: weighted gather; lanes cover feature dim
    constexpr int F = DOUT / 32;
    float acc[F];
#pragma unroll
    for (int f = 0; f < F; f++) acc[f] = 0.f;

    for (int i = o0; i < o1; i++) {
        int src = csr[i];                 // broadcast
        float e = asrc[src] + ad;         // broadcast
        e = leaky(e, 0.2f);
        float alpha = __expf(e - m) * inv;
        const float* hrow = h + (size_t)src * DOUT + lane;
#pragma unroll
        for (int f = 0; f < F; f++)
            acc[f] += alpha * hrow[32 * f];
    }
#pragma unroll
    for (int f = 0; f < F; f++) {
        float v = acc[f] + bias[lane + 32 * f];
        out[n * DOUT + lane + 32 * f] = leaky(v, 0.01f);
    }
}

// ---------------- batchnorm statistics (sum, sumsq per feature) ----------------
template <int DOUT>
__global__ void bnstats(const float* __restrict__ act, float* bnsum, float* bnsq, int N)
{
    constexpr int ROWS = 256 / DOUT;
    int j = threadIdx.x % DOUT;
    int r = threadIdx.x / DOUT;
    float s = 0.f, q = 0.f;
    for (int n = blockIdx.x * ROWS + r; n < N; n += gridDim.x * ROWS) {
        float v = act[n * DOUT + j];
        s += v;
        q += v * v;
    }
    __shared__ float ss[256], sq[256];
    ss[threadIdx.x] = s;
    sq[threadIdx.x] = q;
    __syncthreads();
    if (r == 0) {
        for (int g = 1; g < ROWS; g++) { s += ss[g * DOUT + j]; q += sq[g * DOUT + j]; }
        atomicAdd(&bnsum[j], s);
        atomicAdd(&bnsq[j], q);
    }
}

__global__ void bnfin(const float* __restrict__ bnsum, const float* __restrict__ bnsq,
                      const float* __restrict__ g, const float* __restrict__ be,
                      float* scale, float* shift, int N, int dout)
{
    int j = threadIdx.x;
    if (j >= dout) return;
    float invN = 1.f / (float)N;
    float mu = bnsum[j] * invN;
    float var = bnsq[j] * invN - mu * mu;
    float sc = g[j] * rsqrtf(var + 1e-5f);
    scale[j] = sc;
    shift[j] = be[j] - mu * sc;
}

// ---------------- pooling (batch is sorted => run-length accumulate) ----------------
__global__ void pool_kernel(const float* __restrict__ act, const float* __restrict__ scale,
                            const float* __restrict__ shift, const int* __restrict__ batch,
                            float* pooled, int N)
{
    const int CHUNK = 32;
    int j = threadIdx.x;            // 0..63
    int n0 = blockIdx.x * CHUNK;
    int n1 = n0 + CHUNK; if (n1 > N) n1 = N;
    float sc = scale[j], sh = shift[j];
    float acc = 0.f;
    int cur = -1;
    for (int n = n0; n < n1; n++) {
        int b = batch[n];
        if (b != cur) {
            if (cur >= 0) atomicAdd(&pooled[cur * 64 + j], acc);
            cur = b; acc = 0.f;
        }
        acc += act[n * 64 + j] * sc + sh;
    }
    if (cur >= 0) atomicAdd(&pooled[cur * 64 + j], acc);
}

// ---------------- final MLP + sigmoid ----------------
__global__ void mlp_kernel(const float* __restrict__ pooled, const float* __restrict__ Wf,
                           const float* __restrict__ bf, const float* __restrict__ Wc,
                           const float* __restrict__ bc, float* __restrict__ out, int G)
{
    int g = blockIdx.x;
    __shared__ float p[64];
    __shared__ float z[32];
    int t = threadIdx.x;            // 64 threads
    p[t] = pooled[g * 64 + t];
    __syncthreads();
    if (t < 32) {
        float a = bf[t];
#pragma unroll 8
        for (int k = 0; k < 64; k++) a += p[k] * Wf[k * 32 + t];
        z[t] = leaky(a, 0.01f);
    }
    __syncthreads();
    if (t < 8) {
        float a = bc[t];
#pragma unroll
        for (int jj = 0; jj < 32; jj++) a += z[jj] * Wc[jj * 8 + t];
        out[g * 8 + t] = 1.f / (1.f + expf(-a));
    }
}

// ---------------- host launcher ----------------
extern "C" void kernel_launch(void* const* d_in, const int* in_sizes, int n_in,
                              void* d_out, int out_size)
{
    const float* x     = (const float*)d_in[0];
    const int*   ei    = (const int*)d_in[1];
    const int*   batch = (const int*)d_in[2];
    int N = in_sizes[2];
    int E = in_sizes[1] / 2;
    int G = out_size / 8;
    int ET = E + N;
    float* out = (float*)d_out;

    // parameter pointers (layer i base = 3 + 6*(i-1))
    const float *W[4], *As[4], *Ad[4], *B[4], *Gm[4], *Be[4];
    for (int i = 0; i < 4; i++) {
        int base = 3 + 6 * i;
        W[i]  = (const float*)d_in[base + 0];
        As[i] = (const float*)d_in[base + 1];
        Ad[i] = (const float*)d_in[base + 2];
        B[i]  = (const float*)d_in[base + 3];
        Gm[i] = (const float*)d_in[base + 4];
        Be[i] = (const float*)d_in[base + 5];
    }
    const float* Wf = (const float*)d_in[27];
    const float* bf = (const float*)d_in[28];
    const float* Wc = (const float*)d_in[29];
    const float* bc = (const float*)d_in[30];

    int *deg, *cur, *off, *bsum, *csr;
    float *HA, *HB, *asrc, *adst, *bn, *scale, *shift, *pooled;
    cudaGetSymbolAddress((void**)&deg,    d_deg);
    cudaGetSymbolAddress((void**)&cur,    d_cur);
    cudaGetSymbolAddress((void**)&off,    d_off);
    cudaGetSymbolAddress((void**)&bsum,   d_bsum);
    cudaGetSymbolAddress((void**)&csr,    d_csr);
    cudaGetSymbolAddress((void**)&HA,     d_HA);
    cudaGetSymbolAddress((void**)&HB,     d_HB);
    cudaGetSymbolAddress((void**)&asrc,   d_asrc);
    cudaGetSymbolAddress((void**)&adst,   d_adst);
    cudaGetSymbolAddress((void**)&bn,     d_bn);
    cudaGetSymbolAddress((void**)&scale,  d_scale);
    cudaGetSymbolAddress((void**)&shift,  d_shift);
    cudaGetSymbolAddress((void**)&pooled, d_pooled);

    // ---- build dst-CSR (reused by all 4 layers) ----
    zero_i<<<(N + 255) / 256, 256>>>(deg, N);
    zero_i<<<(N + 255) / 256, 256>>>(cur, N);
    count_deg<<<(ET + 255) / 256, 256>>>(ei, E, N, deg);
    int nb = (N + 511) / 512;
    scan1<<<nb, 512>>>(deg, off, bsum, N);
    scan2<<<1, 128>>>(bsum, nb);
    scan3<<<nb, 512>>>(off, bsum, N);
    fill_csr<<<(ET + 255) / 256, 256>>>(ei, E, N, off, cur, csr);

    int nwb = (N + 7) / 8;   // blocks for warp-per-node kernels (256 thr = 8 warps)

    // ---- layer 1: 128 -> 32 (input = x, no BN affine) ----
    gemm_kernel<128, 32><<<(N + 127) / 128, 256>>>(x, W[0], nullptr, nullptr, HA, N);
    attdot<<<nwb, 256>>>(HA, As[0], Ad[0], asrc, adst, N, 32);
    agg_kernel<32><<<nwb, 256>>>(HA, asrc, adst, off, csr, B[0], HB, N);
    zero_f<<<1, 256>>>(bn, 256);
    bnstats<32><<<256, 256>>>(HB, bn, bn + 128, N);
    bnfin<<<1, 128>>>(bn, bn + 128, Gm[0], Be[0], scale, shift, N, 32);

    // ---- layer 2: 32 -> 64 (BN of layer 1 folded into GEMM load) ----
    gemm_kernel<32, 64><<<(N + 63) / 64, 256>>>(HB, W[1], scale, shift, HA, N);
    attdot<<<nwb, 256>>>(HA, As[1], Ad[1], asrc, adst, N, 64);
    agg_kernel<64><<<nwb, 256>>>(HA, asrc, adst, off, csr, B[1], HB, N);
    zero_f<<<1, 256>>>(bn, 256);
    bnstats<64><<<256, 256>>>(HB, bn, bn + 128, N);
    bnfin<<<1, 128>>>(bn, bn + 128, Gm[1], Be[1], scale, shift, N, 64);

    // ---- layer 3: 64 -> 128 ----
    gemm_kernel<64, 128><<<(N + 31) / 32, 256>>>(HB, W[2], scale, shift, HA, N);
    attdot<<<nwb, 256>>>(HA, As[2], Ad[2], asrc, adst, N, 128);
    agg_kernel<128><<<nwb, 256>>>(HA, asrc, adst, off, csr, B[2], HB, N);
    zero_f<<<1, 256>>>(bn, 256);
    bnstats<128><<<256, 256>>>(HB, bn, bn + 128, N);
    bnfin<<<1, 128>>>(bn, bn + 128, Gm[2], Be[2], scale, shift, N, 128);

    // ---- layer 4: 128 -> 64 ----
    gemm_kernel<128, 64><<<(N + 63) / 64, 256>>>(HB, W[3], scale, shift, HA, N);
    attdot<<<nwb, 256>>>(HA, As[3], Ad[3], asrc, adst, N, 64);
    agg_kernel<64><<<nwb, 256>>>(HA, asrc, adst, off, csr, B[3], HB, N);
    zero_f<<<1, 256>>>(bn, 256);
    bnstats<64><<<256, 256>>>(HB, bn, bn + 128, N);
    bnfin<<<1, 128>>>(bn, bn + 128, Gm[3], Be[3], scale, shift, N, 64);

    // ---- pooling (layer-4 BN affine applied on the fly; batch sorted) ----
    zero_f<<<(G * 64 + 255) / 256, 256>>>(pooled, G * 64);
    pool_kernel<<<(N + 31) / 32, 64>>>(HB, scale, shift, batch, pooled, N);

    // ---- final MLP + sigmoid ----
    mlp_kernel<<<G, 64>>>(pooled, Wf, bf, Wc, bc, out, G);
}

// round 6
// speedup vs baseline: 1.0112x; 1.0036x over previous
#include <cuda_runtime.h>

// ---------------- static scratch (no allocation allowed) ----------------
#define NMAX 50048
#define EMAX 900000
#define FMAX 128

__device__ int   d_deg[NMAX];
__device__ int   d_cur[NMAX];
__device__ int   d_off[NMAX + 1];
__device__ int   d_csr[EMAX];
__device__ float d_HA[NMAX * FMAX];
__device__ float d_HB[NMAX * FMAX];
__device__ float d_asrc[NMAX];
__device__ float d_adst[NMAX];
__device__ float d_bn0[32 * 256];    // 32 shadow copies: [s][0:128)=sum, [s][128:256)=sumsq
__device__ float d_bn1[32 * 256];
__device__ float d_pooled[2048 * 64];

__device__ __forceinline__ float leaky(float x, float s) { return x > 0.f ? x : s * x; }

// ---------------- CSR build ----------------
__global__ void init_kernel(int* deg, int* cur, int N) {
    int i = blockIdx.x * blockDim.x + threadIdx.x;
    if (i < N) { deg[i] = 1; cur[i] = 1; }   // slot 0 reserved for self-loop
}

__global__ void count_deg(const int* __restrict__ ei, int E, int* deg) {
    int e = blockIdx.x * blockDim.x + threadIdx.x;
    if (e < E) atomicAdd(&deg[ei[E + e]], 1);
}

// single-block scan over N<=50048 degrees
__global__ void scan_kernel(const int* __restrict__ deg, int* off, int N) {
    __shared__ int part[1024];
    int t = threadIdx.x;
    int per = (N + 1023) / 1024;
    int start = t * per;
    int end = start + per; if (end > N) end = N;
    int sum = 0;
    for (int i = start; i < end; i++) sum += deg[i];
    part[t] = sum;
    __syncthreads();
    for (int d = 1; d < 1024; d <<= 1) {
        int v = (t >= d) ? part[t - d] : 0;
        __syncthreads();
        part[t] += v;
        __syncthreads();
    }
    int run = (t > 0) ? part[t - 1] : 0;
    for (int i = start; i < end; i++) { run += deg[i]; off[i + 1] = run; }
    if (t == 0) off[0] = 0;
}

// fill CSR (+ self-loops at slot 0, + zero pooled in extra blocks)
__global__ void fill_csr(const int* __restrict__ ei, int E, int N,
                         const int* __restrict__ off, int* cur, int* csr,
                         float* pooled, int PZ) {
    int idx = blockIdx.x * blockDim.x + threadIdx.x;
    if (idx < E) {
        int s = ei[idx], d = ei[E + idx];
        int p = atomicAdd(&cur[d], 1);
        csr[off[d] + p] = s;
    } else if (idx < E + N) {
        int n = idx - E;
        csr[off[n]] = n;
    } else if (idx < E + N + PZ) {
        pooled[idx - E - N] = 0.f;
    }
}

// ---------------- GEMM + fused prev-layer BN affine + fused attention dots ----------------
// Y[N,DOUT] = affine(X) @ W ; asrc[n]=Y[n]·a_s ; adst[n]=Y[n]·a_d
// also zeroes the NEXT layer's bn shadow buffer (block 0)
template <int DIN, int DOUT, int KC>
__global__ __launch_bounds__(256) void gemm_att(
    const float* __restrict__ X, const float* __restrict__ W,
    const float* __restrict__ bnPrev, const float* __restrict__ gamma,
    const float* __restrict__ beta, float* __restrict__ bnNext,
    const float* __restrict__ a_s, const float* __restrict__ a_d,
    float* __restrict__ Y, float* __restrict__ asrc, float* __restrict__ adst, int N)
{
    constexpr int TX = DOUT / 8;
    constexpr int TY = 256 / TX;
    constexpr int ROWS = TY * 4;

    __shared__ float sIn[ROWS][KC + 1];
    __shared__ float sW[KC][DOUT];
    __shared__ float sScale[DIN];
    __shared__ float sShift[DIN];

    int tid = threadIdx.x;

    // inline BN scale/shift from 32-shadow sums of previous layer
    for (int j = tid; j < DIN; j += 256) {
        if (bnPrev) {
            float s = 0.f, q = 0.f;
#pragma unroll
            for (int w = 0; w < 32; w++) {
                s += bnPrev[w * 256 + j];
                q += bnPrev[w * 256 + 128 + j];
            }
            float invN = 1.f / (float)N;
            float mu = s * invN;
            float var = q * invN - mu * mu;
            float sc = gamma[j] * rsqrtf(var + 1e-5f);
            sScale[j] = sc;
            sShift[j] = beta[j] - mu * sc;
        } else {
            sScale[j] = 1.f;
            sShift[j] = 0.f;
        }
    }
    // zero next layer's bn shadows (runs before next agg; different buffer than bnPrev)
    if (blockIdx.x == 0) {
        for (int i = tid; i < 32 * 256; i += 256) bnNext[i] = 0.f;
    }
    __syncthreads();

    int nodeBase = blockIdx.x * ROWS;
    int tx = tid % TX, ty = tid / TX;

    float acc[4][8] = {};

    for (int k0 = 0; k0 < DIN; k0 += KC) {
        for (int i = tid; i < KC * DOUT; i += 256) {
            int kk = i / DOUT, c = i % DOUT;
            sW[kk][c] = W[(k0 + kk) * DOUT + c];
        }
        for (int i = tid; i < ROWS * KC; i += 256) {
            int r = i / KC, c = i % KC;
            int n = nodeBase + r;
            float v = 0.f;
            if (n < N) v = X[n * DIN + k0 + c] * sScale[k0 + c] + sShift[k0 + c];
            sIn[r][c] = v;
        }
        __syncthreads();

#pragma unroll 8
        for (int k = 0; k < KC; k++) {
            float4 wa = *(const float4*)&sW[k][tx * 8];
            float4 wb = *(const float4*)&sW[k][tx * 8 + 4];
            float xv[4];
#pragma unroll
            for (int r = 0; r < 4; r++) xv[r] = sIn[ty * 4 + r][k];
#pragma unroll
            for (int r = 0; r < 4; r++) {
                acc[r][0] += xv[r] * wa.x; acc[r][1] += xv[r] * wa.y;
                acc[r][2] += xv[r] * wa.z; acc[r][3] += xv[r] * wa.w;
                acc[r][4] += xv[r] * wb.x; acc[r][5] += xv[r] * wb.y;
                acc[r][6] += xv[r] * wb.z; acc[r][7] += xv[r] * wb.w;
            }
        }
        __syncthreads();
    }

    // epilogue: store Y + fused attention dot products
    float av_s[8], av_d[8];
#pragma unroll
    for (int c = 0; c < 8; c++) {
        av_s[c] = a_s[tx * 8 + c];
        av_d[c] = a_d[tx * 8 + c];
    }
#pragma unroll
    for (int r = 0; r < 4; r++) {
        int n = nodeBase + ty * 4 + r;
        float ps = 0.f, pd = 0.f;
#pragma unroll
        for (int c = 0; c < 8; c++) { ps += acc[r][c] * av_s[c]; pd += acc[r][c] * av_d[c]; }
#pragma unroll
        for (int o = TX >> 1; o; o >>= 1) {
            ps += __shfl_xor_sync(0xffffffffu, ps, o);
            pd += __shfl_xor_sync(0xffffffffu, pd, o);
        }
        if (n < N) {
            if (tx == 0) { asrc[n] = ps; adst[n] = pd; }
            float4 o1 = make_float4(acc[r][0], acc[r][1], acc[r][2], acc[r][3]);
            float4 o2 = make_float4(acc[r][4], acc[r][5], acc[r][6], acc[r][7]);
            *(float4*)&Y[(size_t)n * DOUT + tx * 8] = o1;
            *(float4*)&Y[(size_t)n * DOUT + tx * 8 + 4] = o2;
        }
    }
}

// ---------------- fused softmax-attention aggregation + BN stats, warp per dst ----------------
template <int DOUT>
__global__ __launch_bounds__(256) void agg_bn(
    const float* __restrict__ h, const float* __restrict__ asrc,
    const float* __restrict__ adst, const int* __restrict__ off,
    const int* __restrict__ csr, const float* __restrict__ bias,
    float* __restrict__ out, float* __restrict__ bnbuf, int N)
{
    constexpr int F = DOUT / 32;
    __shared__ float sS[8][DOUT];
    __shared__ float sQ[8][DOUT];
    int warp = threadIdx.x >> 5, lane = threadIdx.x & 31;
    int n = blockIdx.x * 8 + warp;

    float vout[F];
#pragma unroll
    for (int f = 0; f < F; f++) vout[f] = 0.f;

    if (n < N) {
        int o0 = off[n], o1 = off[n + 1];
        float ad = adst[n];

        // pass A+B: online (max, expsum) over incoming edges
        float m = -1e30f, s = 0.f;
        for (int i = o0 + lane; i < o1; i += 32) {
            float e = leaky(asrc[csr[i]] + ad, 0.2f);
            if (e > m) { s *= __expf(m - e); m = e; }
            s += __expf(e - m);
        }
#pragma unroll
        for (int o = 16; o; o >>= 1) {
            float m2 = __shfl_xor_sync(0xffffffffu, m, o);
            float s2 = __shfl_xor_sync(0xffffffffu, s, o);
            float mm = fmaxf(m, m2);
            s = s * __expf(m - mm) + s2 * __expf(m2 - mm);
            m = mm;
        }
        float inv = 1.f / s;

        // pass C: weighted gather, unrolled x4 for load-level parallelism
        float acc[F];
#pragma unroll
        for (int f = 0; f < F; f++) acc[f] = 0.f;

        int i = o0;
        for (; i + 4 <= o1; i += 4) {
            int s0 = csr[i], s1 = csr[i + 1], s2 = csr[i + 2], s3 = csr[i + 3];
            float w0 = __expf(leaky(asrc[s0] + ad, 0.2f) - m);
            float w1 = __expf(leaky(asrc[s1] + ad, 0.2f) - m);
            float w2 = __expf(leaky(asrc[s2] + ad, 0.2f) - m);
            float w3 = __expf(leaky(asrc[s3] + ad, 0.2f) - m);
            const float* h0 = h + (size_t)s0 * DOUT + lane;
            const float* h1 = h + (size_t)s1 * DOUT + lane;
            const float* h2 = h + (size_t)s2 * DOUT + lane;
            const float* h3 = h + (size_t)s3 * DOUT + lane;
#pragma unroll
            for (int f = 0; f < F; f++)
                acc[f] += w0 * h0[32 * f] + w1 * h1[32 * f] + w2 * h2[32 * f] + w3 * h3[32 * f];
        }
        for (; i < o1; i++) {
            int s0 = csr[i];
            float w0 = __expf(leaky(asrc[s0] + ad, 0.2f) - m);
            const float* h0 = h + (size_t)s0 * DOUT + lane;
#pragma unroll
            for (int f = 0; f < F; f++) acc[f] += w0 * h0[32 * f];
        }

#pragma unroll
        for (int f = 0; f < F; f++) {
            float v = leaky(acc[f] * inv + bias[lane + 32 * f], 0.01f);
            out[(size_t)n * DOUT + lane + 32 * f] = v;
            vout[f] = v;
        }
    }

    // fused BN stats: block reduce then 32-shadow global atomics
#pragma unroll
    for (int f = 0; f < F; f++) {
        sS[warp][lane + 32 * f] = vout[f];
        sQ[warp][lane + 32 * f] = vout[f] * vout[f];
    }
    __syncthreads();
    int shadow = (blockIdx.x & 31) * 256;
    for (int j = threadIdx.x; j < DOUT; j += 256) {
        float a = 0.f, b = 0.f;
#pragma unroll
        for (int w = 0; w < 8; w++) { a += sS[w][j]; b += sQ[w][j]; }
        atomicAdd(&bnbuf[shadow + j], a);
        atomicAdd(&bnbuf[shadow + 128 + j], b);
    }
}

// ---------------- pooling: inline layer-4 BN affine, batch sorted => run-length ----------------
__global__ void pool_kernel(const float* __restrict__ act, const float* __restrict__ bnbuf,
                            const float* __restrict__ g, const float* __restrict__ be,
                            const int* __restrict__ batch, float* pooled, int N)
{
    int j = threadIdx.x;            // 0..63
    float s = 0.f, q = 0.f;
#pragma unroll
    for (int w = 0; w < 32; w++) { s += bnbuf[w * 256 + j]; q += bnbuf[w * 256 + 128 + j]; }
    float invN = 1.f / (float)N;
    float mu = s * invN;
    float var = q * invN - mu * mu;
    float sc = g[j] * rsqrtf(var + 1e-5f);
    float sh = be[j] - mu * sc;

    int n0 = blockIdx.x * 32;
    int n1 = n0 + 32; if (n1 > N) n1 = N;
    float acc = 0.f;
    int cur = -1;
    for (int n = n0; n < n1; n++) {
        int b = batch[n];
        if (b != cur) {
            if (cur >= 0) atomicAdd(&pooled[cur * 64 + j], acc);
            cur = b; acc = 0.f;
        }
        acc += act[(size_t)n * 64 + j] * sc + sh;
    }
    if (cur >= 0) atomicAdd(&pooled[cur * 64 + j], acc);
}

// ---------------- final MLP + sigmoid ----------------
__global__ void mlp_kernel(const float* __restrict__ pooled, const float* __restrict__ Wf,
                           const float* __restrict__ bf, const float* __restrict__ Wc,
                           const float* __restrict__ bc, float* __restrict__ out, int G)
{
    int g = blockIdx.x;
    __shared__ float p[64];
    __shared__ float z[32];
    int t = threadIdx.x;            // 64 threads
    p[t] = pooled[g * 64 + t];
    __syncthreads();
    if (t < 32) {
        float a = bf[t];
#pragma unroll 8
        for (int k = 0; k < 64; k++) a += p[k] * Wf[k * 32 + t];
        z[t] = leaky(a, 0.01f);
    }
    __syncthreads();
    if (t < 8) {
        float a = bc[t];
#pragma unroll
        for (int jj = 0; jj < 32; jj++) a += z[jj] * Wc[jj * 8 + t];
        out[g * 8 + t] = 1.f / (1.f + expf(-a));
    }
}

// ---------------- host launcher (14 kernel launches) ----------------
extern "C" void kernel_launch(void* const* d_in, const int* in_sizes, int n_in,
                              void* d_out, int out_size)
{
    const float* x     = (const float*)d_in[0];
    const int*   ei    = (const int*)d_in[1];
    const int*   batch = (const int*)d_in[2];
    int N = in_sizes[2];
    int E = in_sizes[1] / 2;
    int G = out_size / 8;
    float* out = (float*)d_out;

    const float *W[4], *As[4], *Ad[4], *B[4], *Gm[4], *Be[4];
    for (int i = 0; i < 4; i++) {
        int base = 3 + 6 * i;
        W[i]  = (const float*)d_in[base + 0];
        As[i] = (const float*)d_in[base + 1];
        Ad[i] = (const float*)d_in[base + 2];
        B[i]  = (const float*)d_in[base + 3];
        Gm[i] = (const float*)d_in[base + 4];
        Be[i] = (const float*)d_in[base + 5];
    }
    const float* Wf = (const float*)d_in[27];
    const float* bf = (const float*)d_in[28];
    const float* Wc = (const float*)d_in[29];
    const float* bc = (const float*)d_in[30];

    int *deg, *cur, *off, *csr;
    float *HA, *HB, *asrc, *adst, *bn0, *bn1, *pooled;
    cudaGetSymbolAddress((void**)&deg,    d_deg);
    cudaGetSymbolAddress((void**)&cur,    d_cur);
    cudaGetSymbolAddress((void**)&off,    d_off);
    cudaGetSymbolAddress((void**)&csr,    d_csr);
    cudaGetSymbolAddress((void**)&HA,     d_HA);
    cudaGetSymbolAddress((void**)&HB,     d_HB);
    cudaGetSymbolAddress((void**)&asrc,   d_asrc);
    cudaGetSymbolAddress((void**)&adst,   d_adst);
    cudaGetSymbolAddress((void**)&bn0,    d_bn0);
    cudaGetSymbolAddress((void**)&bn1,    d_bn1);
    cudaGetSymbolAddress((void**)&pooled, d_pooled);

    // ---- build dst-CSR (slot 0 per node = self loop; atomics only for real edges) ----
    init_kernel<<<(N + 255) / 256, 256>>>(deg, cur, N);
    count_deg<<<(E + 255) / 256, 256>>>(ei, E, deg);
    scan_kernel<<<1, 1024>>>(deg, off, N);
    int PZ = G * 64;
    fill_csr<<<(E + N + PZ + 255) / 256, 256>>>(ei, E, N, off, cur, csr, pooled, PZ);

    int nwb = (N + 7) / 8;   // warp-per-node blocks (256 thr = 8 warps)

    // layer 0: 128 -> 32   (no BN affine in; zeroes bn0)
    gemm_att<128, 32, 32><<<(N + 255) / 256, 256>>>(
        x, W[0], nullptr, nullptr, nullptr, bn0, As[0], Ad[0], HA, asrc, adst, N);
    agg_bn<32><<<nwb, 256>>>(HA, asrc, adst, off, csr, B[0], HB, bn0, N);

    // layer 1: 32 -> 64    (BN0 affine fused; zeroes bn1)
    gemm_att<32, 64, 32><<<(N + 127) / 128, 256>>>(
        HB, W[1], bn0, Gm[0], Be[0], bn1, As[1], Ad[1], HA, asrc, adst, N);
    agg_bn<64><<<nwb, 256>>>(HA, asrc, adst, off, csr, B[1], HB, bn1, N);

    // layer 2: 64 -> 128   (BN1 affine fused; zeroes bn0)
    gemm_att<64, 128, 32><<<(N + 63) / 64, 256>>>(
        HB, W[2], bn1, Gm[1], Be[1], bn0, As[2], Ad[2], HA, asrc, adst, N);
    agg_bn<128><<<nwb, 256>>>(HA, asrc, adst, off, csr, B[2], HB, bn0, N);

    // layer 3: 128 -> 64   (BN2 affine fused; zeroes bn1)
    gemm_att<128, 64, 32><<<(N + 127) / 128, 256>>>(
        HB, W[3], bn0, Gm[2], Be[2], bn1, As[3], Ad[3], HA, asrc, adst, N);
    agg_bn<64><<<nwb, 256>>>(HA, asrc, adst, off, csr, B[3], HB, bn1, N);

    // pooling (BN3 affine inline; pooled was zeroed in fill_csr)
    pool_kernel<<<(N + 31) / 32, 64>>>(HB, bn1, Gm[3], Be[3], batch, pooled, N);

    // final MLP + sigmoid
    mlp_kernel<<<G, 64>>>(pooled, Wf, bf, Wc, bc, out, G);
}